// round 1
// baseline (speedup 1.0000x reference)
#include <cuda_runtime.h>
#include <math.h>

#define N_ATOMS 8192
#define D_DIM   128
#define K_MAX   4224
#define TWO_PI  6.28318530717958647692f

// ---------------- static device scratch (no runtime allocation) ----------------
__device__ float g_cosf[(size_t)K_MAX * N_ATOMS];   // [K][N]  cos of +phase_f
__device__ float g_sinf[(size_t)K_MAX * N_ATOMS];   // [K][N]  sin of +phase_f
__device__ float g_cosi[(size_t)N_ATOMS * K_MAX];   // [N][K]  cos(phase_i)
__device__ float g_sini[(size_t)N_ATOMS * K_MAX];   // [N][K]  sin(phase_i)
__device__ float g_kpr[K_MAX * D_DIM];
__device__ float g_kpi[K_MAX * D_DIM];
__device__ float g_vpr[K_MAX * D_DIM];
__device__ float g_vpi[K_MAX * D_DIM];
__device__ float g_akp[K_MAX * D_DIM];              // |k_pot|
__device__ float g_qabs[(size_t)N_ATOMS * D_DIM];
__device__ float g_aw[(size_t)N_ATOMS * K_MAX];     // aw, then softmax in place

// ---------------- helpers ----------------
__device__ __forceinline__ void build_tables_one(
    float rx, float ry, float rz,
    float* exr, float* exi, float* eyr, float* eyi,
    float* ezr, float* ezi, int pitch)
{
    #pragma unroll
    for (int j = 0; j <= 12; j++) {
        float s, c;
        sincosf(TWO_PI * rx * (float)j, &s, &c);
        exr[j * pitch] = c; exi[j * pitch] = s;
    }
    #pragma unroll
    for (int j = 0; j <= 12; j++) {
        float s, c;
        sincosf(TWO_PI * ry * (float)j, &s, &c);
        eyr[(12 + j) * pitch] = c; eyi[(12 + j) * pitch] = s;
        eyr[(12 - j) * pitch] = c; eyi[(12 - j) * pitch] = -s;
    }
    #pragma unroll
    for (int j = 0; j <= 12; j++) {
        float s, c;
        sincosf(TWO_PI * rz * (float)j, &s, &c);
        ezr[(12 + j) * pitch] = c; ezi[(12 + j) * pitch] = s;
        ezr[(12 - j) * pitch] = c; ezi[(12 - j) * pitch] = -s;
    }
}

// ---------------- kernel 1a: forward E matrix, layout [K][N] ----------------
// block: (32,8) threads, 32 atoms per block; grid: N/32
__global__ void __launch_bounds__(256) k_build_fwd(
    const float* __restrict__ pos, const float* __restrict__ cell,
    const int* __restrict__ kfwd, int K)
{
    __shared__ float exr[13][32], exi[13][32];
    __shared__ float eyr[25][32], eyi[25][32];
    __shared__ float ezr[25][32], ezi[25][32];

    const int tx = threadIdx.x;      // atom lane
    const int ty = threadIdx.y;      // k stride lane
    const int n0 = blockIdx.x * 32;

    if (ty == 0) {
        int n = n0 + tx;
        float bx = cell[0], by = cell[4], bz = cell[8];
        float rx = pos[n * 3 + 0] / bx;
        float ry = pos[n * 3 + 1] / by;
        float rz = pos[n * 3 + 2] / bz;
        build_tables_one(rx, ry, rz,
                         &exr[0][tx], &exi[0][tx],
                         &eyr[0][tx], &eyi[0][tx],
                         &ezr[0][tx], &ezi[0][tx], 32);
    }
    __syncthreads();

    for (int k = ty; k < K; k += 8) {
        int a = kfwd[3 * k + 0];
        int b = kfwd[3 * k + 1] + 12;
        int c = kfwd[3 * k + 2] + 12;
        float xr = exr[a][tx], xi = exi[a][tx];
        float yr = eyr[b][tx], yi = eyi[b][tx];
        float zr = ezr[c][tx], zi = ezi[c][tx];
        float pr = xr * yr - xi * yi;
        float pi = xr * yi + xi * yr;
        float er = pr * zr - pi * zi;
        float ei = pr * zi + pi * zr;
        unsigned idx = (unsigned)k * N_ATOMS + n0 + tx;
        g_cosf[idx] = er;
        g_sinf[idx] = ei;
    }
}

// ---------------- kernel 1b: inverse E matrix, layout [N][K] ----------------
// block: (32,8): tx = k lane, ty = atom (8 per block); grid: N/8
__global__ void __launch_bounds__(256) k_build_inv(
    const float* __restrict__ pos, const float* __restrict__ cell,
    const int* __restrict__ kinv, int K)
{
    __shared__ float exr[13][9], exi[13][9];
    __shared__ float eyr[25][9], eyi[25][9];
    __shared__ float ezr[25][9], ezi[25][9];

    const int tx = threadIdx.x;
    const int ty = threadIdx.y;
    const int tid = tx + 32 * ty;
    const int n0 = blockIdx.x * 8;

    if (tid < 8) {
        int n = n0 + tid;
        float bx = cell[0], by = cell[4], bz = cell[8];
        float rx = pos[n * 3 + 0] / bx;
        float ry = pos[n * 3 + 1] / by;
        float rz = pos[n * 3 + 2] / bz;
        build_tables_one(rx, ry, rz,
                         &exr[0][tid], &exi[0][tid],
                         &eyr[0][tid], &eyi[0][tid],
                         &ezr[0][tid], &ezi[0][tid], 9);
    }
    __syncthreads();

    for (int k = tx; k < K; k += 32) {
        int a = kinv[3 * k + 0];
        int b = kinv[3 * k + 1] + 12;
        int c = kinv[3 * k + 2] + 12;
        float xr = exr[a][ty], xi = exi[a][ty];
        float yr = eyr[b][ty], yi = eyi[b][ty];
        float zr = ezr[c][ty], zi = ezi[c][ty];
        float pr = xr * yr - xi * yi;
        float pi = xr * yi + xi * yr;
        float er = pr * zr - pi * zi;
        float ei = pr * zi + pi * zr;
        // eik_i = exp(-i*phase) = cos - i sin; Re(eik_i * (vr+i vi)) = cos*vr + sin*vi
        size_t idx = (size_t)(n0 + ty) * K + k;
        g_cosi[idx] = er;
        g_sini[idx] = ei;
    }
}

// ---------------- kernel 1c: |q| ----------------
__global__ void k_absq(const float* __restrict__ q)
{
    int i = blockIdx.x * 256 + threadIdx.x;
    g_qabs[i] = fabsf(q[i]);
}

#define FMA4(acc, a, b) { (acc).x += (a)*(b).x; (acc).y += (a)*(b).y; \
                          (acc).z += (a)*(b).z; (acc).w += (a)*(b).w; }

// ---------------- kernel 2: phase A GEMM (k_pot / v_pot) ----------------
// out tile: 16 k-rows x 128 d; reduce over N in chunks of 32. 256 threads.
__global__ void __launch_bounds__(256) k_phaseA(
    const float* __restrict__ kv, const float* __restrict__ vv, int K)
{
    __shared__ float s_c[32][17], s_s[32][17];   // [n][krow]
    __shared__ float s_k[32][128], s_v[32][128]; // [n][d]

    const int t  = threadIdx.x;
    const int tx = t & 31;   // d group: cols tx*4..tx*4+3
    const int ty = t >> 5;   // k rows ty, ty+8
    const int k0 = blockIdx.x * 16;
    const int r0 = ty, r1 = ty + 8;
    const bool g0 = (k0 + r0) < K;
    const bool g1 = (k0 + r1) < K;

    float4 kr0 = {0,0,0,0}, kr1 = {0,0,0,0}, ki0 = {0,0,0,0}, ki1 = {0,0,0,0};
    float4 vr0 = {0,0,0,0}, vr1 = {0,0,0,0}, vi0 = {0,0,0,0}, vi1 = {0,0,0,0};

    for (int nb = 0; nb < N_ATOMS; nb += 32) {
        __syncthreads();
        {
            unsigned i0 = (unsigned)(k0 + r0) * N_ATOMS + nb + tx;
            unsigned i1 = (unsigned)(k0 + r1) * N_ATOMS + nb + tx;
            s_c[tx][r0] = g0 ? g_cosf[i0] : 0.f;
            s_s[tx][r0] = g0 ? g_sinf[i0] : 0.f;
            s_c[tx][r1] = g1 ? g_cosf[i1] : 0.f;
            s_s[tx][r1] = g1 ? g_sinf[i1] : 0.f;
        }
        #pragma unroll
        for (int i = 0; i < 4; i++) {
            int row = ty + 8 * i;
            float4 a = *(const float4*)&kv[(size_t)(nb + row) * 128 + tx * 4];
            float4 b = *(const float4*)&vv[(size_t)(nb + row) * 128 + tx * 4];
            *(float4*)&s_k[row][tx * 4] = a;
            *(float4*)&s_v[row][tx * 4] = b;
        }
        __syncthreads();
        #pragma unroll
        for (int nn = 0; nn < 32; nn++) {
            float c0 = s_c[nn][r0], c1 = s_c[nn][r1];
            float q0 = s_s[nn][r0], q1 = s_s[nn][r1];
            float4 bk = *(const float4*)&s_k[nn][tx * 4];
            float4 bv = *(const float4*)&s_v[nn][tx * 4];
            FMA4(kr0, c0, bk); FMA4(kr1, c1, bk);
            FMA4(ki0, q0, bk); FMA4(ki1, q1, bk);
            FMA4(vr0, c0, bv); FMA4(vr1, c1, bv);
            FMA4(vi0, q0, bv); FMA4(vi1, q1, bv);
        }
    }
    if (g0) {
        int o = (k0 + r0) * 128 + tx * 4;
        *(float4*)&g_kpr[o] = kr0; *(float4*)&g_kpi[o] = ki0;
        *(float4*)&g_vpr[o] = vr0; *(float4*)&g_vpi[o] = vi0;
    }
    if (g1) {
        int o = (k0 + r1) * 128 + tx * 4;
        *(float4*)&g_kpr[o] = kr1; *(float4*)&g_kpi[o] = ki1;
        *(float4*)&g_vpr[o] = vr1; *(float4*)&g_vpi[o] = vi1;
    }
}

// ---------------- kernel 3: |k_pot| ----------------
__global__ void k_abspot(int K)
{
    int i = blockIdx.x * 256 + threadIdx.x;
    if (i < K * 128) {
        float r = g_kpr[i], im = g_kpi[i];
        g_akp[i] = sqrtf(r * r + im * im);
    }
}

// ---------------- kernel 4: aw = |q| @ |k_pot|^T ----------------
// tile: 128 n x 64 k; reduce D=128 in chunks of 16. 256 threads (16x16).
__global__ void __launch_bounds__(256) k_phaseB(int K)
{
    __shared__ float s_a[16][132];  // [d][n]
    __shared__ float s_b[16][68];   // [d][k]

    const int t  = threadIdx.x;
    const int tx = t & 15;     // k cols tx*4..+3
    const int ty = t >> 4;     // n rows ty*8..+7
    const int kb = blockIdx.x * 64;
    const int nb = blockIdx.y * 128;

    float4 acc[8];
    #pragma unroll
    for (int i = 0; i < 8; i++) acc[i] = make_float4(0.f, 0.f, 0.f, 0.f);

    for (int d0 = 0; d0 < 128; d0 += 16) {
        __syncthreads();
        #pragma unroll
        for (int i = 0; i < 8; i++) {
            int r = (t >> 4) + 16 * i;
            s_a[t & 15][r] = g_qabs[(size_t)(nb + r) * 128 + d0 + (t & 15)];
        }
        #pragma unroll
        for (int i = 0; i < 4; i++) {
            int r = (t >> 4) + 16 * i;
            float v = (kb + r < K) ? g_akp[(kb + r) * 128 + d0 + (t & 15)] : 0.f;
            s_b[t & 15][r] = v;
        }
        __syncthreads();
        #pragma unroll
        for (int dd = 0; dd < 16; dd++) {
            float4 b  = *(const float4*)&s_b[dd][tx * 4];
            float4 a0 = *(const float4*)&s_a[dd][ty * 8];
            float4 a1 = *(const float4*)&s_a[dd][ty * 8 + 4];
            FMA4(acc[0], a0.x, b); FMA4(acc[1], a0.y, b);
            FMA4(acc[2], a0.z, b); FMA4(acc[3], a0.w, b);
            FMA4(acc[4], a1.x, b); FMA4(acc[5], a1.y, b);
            FMA4(acc[6], a1.z, b); FMA4(acc[7], a1.w, b);
        }
    }
    #pragma unroll
    for (int i = 0; i < 8; i++) {
        int n = nb + ty * 8 + i;
        size_t base = (size_t)n * K + kb + tx * 4;
        float vals[4] = {acc[i].x, acc[i].y, acc[i].z, acc[i].w};
        #pragma unroll
        for (int j = 0; j < 4; j++)
            if (kb + tx * 4 + j < K) g_aw[base + j] = vals[j];
    }
}

// ---------------- kernel 5: row softmax in place ----------------
__global__ void __launch_bounds__(256) k_softmax(int K)
{
    __shared__ float buf[K_MAX];
    __shared__ float red[8];
    const int n = blockIdx.x;
    const int t = threadIdx.x;
    float* row = g_aw + (size_t)n * K;

    float mx = -1e30f;
    for (int i = t; i < K; i += 256) {
        float v = row[i];
        buf[i] = v;
        mx = fmaxf(mx, v);
    }
    #pragma unroll
    for (int o = 16; o; o >>= 1) mx = fmaxf(mx, __shfl_xor_sync(0xffffffffu, mx, o));
    if ((t & 31) == 0) red[t >> 5] = mx;
    __syncthreads();
    float gmax = red[0];
    #pragma unroll
    for (int j = 1; j < 8; j++) gmax = fmaxf(gmax, red[j]);
    __syncthreads();

    float s = 0.f;
    for (int i = t; i < K; i += 256) {
        float e = expf(buf[i] - gmax);
        buf[i] = e;
        s += e;
    }
    #pragma unroll
    for (int o = 16; o; o >>= 1) s += __shfl_xor_sync(0xffffffffu, s, o);
    if ((t & 31) == 0) red[t >> 5] = s;
    __syncthreads();
    float gsum = 0.f;
    #pragma unroll
    for (int j = 0; j < 8; j++) gsum += red[j];
    float inv = 1.f / gsum;

    for (int i = t; i < K; i += 256) row[i] = buf[i] * inv;
}

// ---------------- kernel 6: out = sum_k sm*(cosI*vpr + sinI*vpi) ----------------
// tile: 32 n x 128 d; reduce K in chunks of 32. 256 threads.
__global__ void __launch_bounds__(256) k_phaseD(float* __restrict__ out, int K)
{
    __shared__ float s_wr[32][36], s_wi[32][36];   // [k][n]
    __shared__ float s_vr[32][128], s_vi[32][128]; // [k][d]

    const int t  = threadIdx.x;
    const int tx = t & 31;   // d group: cols tx*4..+3
    const int tg = t >> 5;   // n group: rows tg*4..+3
    const int n0 = blockIdx.x * 32;

    float4 acc[4];
    #pragma unroll
    for (int i = 0; i < 4; i++) acc[i] = make_float4(0.f, 0.f, 0.f, 0.f);

    const int ksteps = (K + 31) / 32;
    for (int ks = 0; ks < ksteps; ks++) {
        int k0 = ks * 32;
        __syncthreads();
        #pragma unroll
        for (int i = 0; i < 4; i++) {
            int r = tg * 4 + i;           // n offset within tile
            int k = k0 + tx;
            float sm = 0.f, ci = 0.f, si = 0.f;
            if (k < K) {
                size_t idx = (size_t)(n0 + r) * K + k;
                sm = g_aw[idx]; ci = g_cosi[idx]; si = g_sini[idx];
            }
            s_wr[tx][r] = sm * ci;
            s_wi[tx][r] = sm * si;
        }
        #pragma unroll
        for (int i = 0; i < 4; i++) {
            int r = tg * 4 + i;           // k offset within tile
            float4 a = make_float4(0.f, 0.f, 0.f, 0.f);
            float4 b = make_float4(0.f, 0.f, 0.f, 0.f);
            if (k0 + r < K) {
                a = *(const float4*)&g_vpr[(k0 + r) * 128 + tx * 4];
                b = *(const float4*)&g_vpi[(k0 + r) * 128 + tx * 4];
            }
            *(float4*)&s_vr[r][tx * 4] = a;
            *(float4*)&s_vi[r][tx * 4] = b;
        }
        __syncthreads();
        #pragma unroll
        for (int kk = 0; kk < 32; kk++) {
            float4 wr = *(const float4*)&s_wr[kk][tg * 4];
            float4 wi = *(const float4*)&s_wi[kk][tg * 4];
            float4 vr = *(const float4*)&s_vr[kk][tx * 4];
            float4 vi = *(const float4*)&s_vi[kk][tx * 4];
            FMA4(acc[0], wr.x, vr); FMA4(acc[0], wi.x, vi);
            FMA4(acc[1], wr.y, vr); FMA4(acc[1], wi.y, vi);
            FMA4(acc[2], wr.z, vr); FMA4(acc[2], wi.z, vi);
            FMA4(acc[3], wr.w, vr); FMA4(acc[3], wi.w, vi);
        }
    }
    #pragma unroll
    for (int i = 0; i < 4; i++) {
        int n = n0 + tg * 4 + i;
        *(float4*)&out[(size_t)n * 128 + tx * 4] = acc[i];
    }
}

// ---------------- launch ----------------
extern "C" void kernel_launch(void* const* d_in, const int* in_sizes, int n_in,
                              void* d_out, int out_size)
{
    const float* q    = (const float*)d_in[0];
    const float* kvec = (const float*)d_in[1];
    const float* vvec = (const float*)d_in[2];
    const float* pos  = (const float*)d_in[3];
    const float* cell = (const float*)d_in[4];
    const int*   kfwd = (const int*)d_in[6];
    const int*   kinv = (const int*)d_in[7];
    const int K = in_sizes[6] / 3;

    dim3 b(32, 8);
    k_build_fwd<<<N_ATOMS / 32, b>>>(pos, cell, kfwd, K);
    k_build_inv<<<N_ATOMS / 8, b>>>(pos, cell, kinv, K);
    k_absq<<<(N_ATOMS * D_DIM) / 256, 256>>>(q);
    k_phaseA<<<(K + 15) / 16, 256>>>(kvec, vvec, K);
    k_abspot<<<(K * D_DIM + 255) / 256, 256>>>(K);
    dim3 gB((K + 63) / 64, N_ATOMS / 128);
    k_phaseB<<<gB, 256>>>(K);
    k_softmax<<<N_ATOMS, 256>>>(K);
    k_phaseD<<<N_ATOMS / 32, 256>>>((float*)d_out, K);
}

// round 2
// speedup vs baseline: 1.4388x; 1.4388x over previous
#include <cuda_runtime.h>
#include <math.h>

#define N_ATOMS 8192
#define D_DIM   128
#define K_MAX   4224
#define SPLIT_A 8
#define TWO_PI  6.28318530717958647692f

typedef unsigned long long u64;

// ---------------- static device scratch ----------------
__device__ float g_cosf[(size_t)K_MAX * N_ATOMS];   // [K][N]
__device__ float g_sinf[(size_t)K_MAX * N_ATOMS];   // [K][N]
__device__ float g_cosi[(size_t)N_ATOMS * K_MAX];   // [N][K]
__device__ float g_sini[(size_t)N_ATOMS * K_MAX];   // [N][K]
__device__ u64   g_pK[SPLIT_A][(size_t)K_MAX * D_DIM];  // {kpr,kpi} partials
__device__ u64   g_pV[SPLIT_A][(size_t)K_MAX * D_DIM];  // {vpr,vpi} partials
__device__ float g_kpr[K_MAX * D_DIM];
__device__ float g_kpi[K_MAX * D_DIM];
__device__ float g_vpr[K_MAX * D_DIM];
__device__ float g_vpi[K_MAX * D_DIM];
__device__ float g_akp[K_MAX * D_DIM];
__device__ float g_qabs[(size_t)N_ATOMS * D_DIM];
__device__ float g_aw[(size_t)N_ATOMS * K_MAX];
__device__ u64   g_pD[2][(size_t)N_ATOMS * 64];     // phase D split partials (float2 pairs)

// ---------------- f32x2 helpers ----------------
__device__ __forceinline__ u64 pk2(float lo, float hi) {
    u64 r; asm("mov.b64 %0,{%1,%2};" : "=l"(r) : "f"(lo), "f"(hi)); return r;
}
__device__ __forceinline__ u64 dup2(float x) { return pk2(x, x); }
__device__ __forceinline__ void fma2(u64& d, u64 a, u64 b) {
    asm("fma.rn.f32x2 %0,%1,%2,%0;" : "+l"(d) : "l"(a), "l"(b));
}
__device__ __forceinline__ float2 up2(u64 v) {
    float2 f; asm("mov.b64 {%0,%1},%2;" : "=f"(f.x), "=f"(f.y) : "l"(v)); return f;
}

// ---------------- plane-wave table helper ----------------
__device__ __forceinline__ void build_tables_one(
    float rx, float ry, float rz,
    float* exr, float* exi, float* eyr, float* eyi,
    float* ezr, float* ezi, int pitch)
{
    #pragma unroll
    for (int j = 0; j <= 12; j++) {
        float s, c;
        sincosf(TWO_PI * rx * (float)j, &s, &c);
        exr[j * pitch] = c; exi[j * pitch] = s;
    }
    #pragma unroll
    for (int j = 0; j <= 12; j++) {
        float s, c;
        sincosf(TWO_PI * ry * (float)j, &s, &c);
        eyr[(12 + j) * pitch] = c; eyi[(12 + j) * pitch] = s;
        eyr[(12 - j) * pitch] = c; eyi[(12 - j) * pitch] = -s;
    }
    #pragma unroll
    for (int j = 0; j <= 12; j++) {
        float s, c;
        sincosf(TWO_PI * rz * (float)j, &s, &c);
        ezr[(12 + j) * pitch] = c; ezi[(12 + j) * pitch] = s;
        ezr[(12 - j) * pitch] = c; ezi[(12 - j) * pitch] = -s;
    }
}

// ---------------- kernel 1a: forward E matrix [K][N] ----------------
__global__ void __launch_bounds__(256) k_build_fwd(
    const float* __restrict__ pos, const float* __restrict__ cell,
    const int* __restrict__ kfwd, int K)
{
    __shared__ float exr[13][32], exi[13][32];
    __shared__ float eyr[25][32], eyi[25][32];
    __shared__ float ezr[25][32], ezi[25][32];

    const int tx = threadIdx.x, ty = threadIdx.y;
    const int n0 = blockIdx.x * 32;

    if (ty == 0) {
        int n = n0 + tx;
        float bx = cell[0], by = cell[4], bz = cell[8];
        build_tables_one(pos[n*3+0]/bx, pos[n*3+1]/by, pos[n*3+2]/bz,
                         &exr[0][tx], &exi[0][tx], &eyr[0][tx], &eyi[0][tx],
                         &ezr[0][tx], &ezi[0][tx], 32);
    }
    __syncthreads();

    for (int k = ty; k < K; k += 8) {
        int a = kfwd[3*k+0], b = kfwd[3*k+1] + 12, c = kfwd[3*k+2] + 12;
        float xr = exr[a][tx], xi = exi[a][tx];
        float yr = eyr[b][tx], yi = eyi[b][tx];
        float zr = ezr[c][tx], zi = ezi[c][tx];
        float pr = xr*yr - xi*yi, pi = xr*yi + xi*yr;
        unsigned idx = (unsigned)k * N_ATOMS + n0 + tx;
        g_cosf[idx] = pr*zr - pi*zi;
        g_sinf[idx] = pr*zi + pi*zr;
    }
}

// ---------------- kernel 1b: inverse E matrix [N][K] ----------------
__global__ void __launch_bounds__(256) k_build_inv(
    const float* __restrict__ pos, const float* __restrict__ cell,
    const int* __restrict__ kinv, int K)
{
    __shared__ float exr[13][9], exi[13][9];
    __shared__ float eyr[25][9], eyi[25][9];
    __shared__ float ezr[25][9], ezi[25][9];

    const int tx = threadIdx.x, ty = threadIdx.y;
    const int tid = tx + 32 * ty;
    const int n0 = blockIdx.x * 8;

    if (tid < 8) {
        int n = n0 + tid;
        float bx = cell[0], by = cell[4], bz = cell[8];
        build_tables_one(pos[n*3+0]/bx, pos[n*3+1]/by, pos[n*3+2]/bz,
                         &exr[0][tid], &exi[0][tid], &eyr[0][tid], &eyi[0][tid],
                         &ezr[0][tid], &ezi[0][tid], 9);
    }
    __syncthreads();

    for (int k = tx; k < K; k += 32) {
        int a = kinv[3*k+0], b = kinv[3*k+1] + 12, c = kinv[3*k+2] + 12;
        float xr = exr[a][ty], xi = exi[a][ty];
        float yr = eyr[b][ty], yi = eyi[b][ty];
        float zr = ezr[c][ty], zi = ezi[c][ty];
        float pr = xr*yr - xi*yi, pi = xr*yi + xi*yr;
        size_t idx = (size_t)(n0 + ty) * K + k;
        g_cosi[idx] = pr*zr - pi*zi;
        g_sini[idx] = pr*zi + pi*zr;
    }
}

// ---------------- kernel 1c: |q| ----------------
__global__ void k_absq(const float* __restrict__ q)
{
    int i = blockIdx.x * 256 + threadIdx.x;
    g_qabs[i] = fabsf(q[i]);
}

// ---------------- kernel 2: phase A split-N GEMM (packed f32x2) ----------------
// tile 32k x 128d; thread: 4 k-rows x 4 d-cols (strided). N chunk = 1024 per split.
__global__ void __launch_bounds__(256, 2) k_phaseA(
    const float* __restrict__ kv, const float* __restrict__ vv, int K)
{
    __shared__ float2 s_cs[32][32];         // [kl][n]  {cos,sin}
    __shared__ float  s_k[32][128];         // [n][d]
    __shared__ float  s_v[32][128];

    const int t  = threadIdx.x;
    const int tx = t & 31;                  // d lane (cols tx + 32m)
    const int ty = t >> 5;                  // row group (rows ty*4+j)
    const int k0 = blockIdx.x * 32;
    const int nb0 = blockIdx.y * (N_ATOMS / SPLIT_A);
    const int nb_end = nb0 + (N_ATOMS / SPLIT_A);

    u64 aK[4][4], aV[4][4];
    #pragma unroll
    for (int j = 0; j < 4; j++)
        #pragma unroll
        for (int m = 0; m < 4; m++) { aK[j][m] = 0ull; aV[j][m] = 0ull; }

    for (int nb = nb0; nb < nb_end; nb += 32) {
        __syncthreads();
        // fill cos/sin (interleaved): thread loads 4 rows at n=tx
        #pragma unroll
        for (int j = 0; j < 4; j++) {
            int kl = ty + 8 * j;
            unsigned gi = (unsigned)(k0 + kl) * N_ATOMS + nb + tx;
            s_cs[kl][tx] = make_float2(g_cosf[gi], g_sinf[gi]);
        }
        // fill k/v raw
        #pragma unroll
        for (int j = 0; j < 4; j++) {
            int row = ty + 8 * j;
            *(float4*)&s_k[row][tx*4] = *(const float4*)&kv[(size_t)(nb+row)*128 + tx*4];
            *(float4*)&s_v[row][tx*4] = *(const float4*)&vv[(size_t)(nb+row)*128 + tx*4];
        }
        __syncthreads();

        #pragma unroll
        for (int nn = 0; nn < 32; nn++) {
            u64 CS[4];
            #pragma unroll
            for (int j = 0; j < 4; j++)
                CS[j] = *(const u64*)&s_cs[ty*4 + j][nn];
            #pragma unroll
            for (int m = 0; m < 4; m++) {
                int d = tx + 32 * m;
                u64 Kd = dup2(s_k[nn][d]);
                u64 Vd = dup2(s_v[nn][d]);
                #pragma unroll
                for (int j = 0; j < 4; j++) {
                    fma2(aK[j][m], CS[j], Kd);   // {sum c*k, sum s*k}
                    fma2(aV[j][m], CS[j], Vd);   // {sum c*v, sum s*v}
                }
            }
        }
    }

    const int sp = blockIdx.y;
    #pragma unroll
    for (int j = 0; j < 4; j++) {
        int k = k0 + ty*4 + j;
        if (k < K) {
            #pragma unroll
            for (int m = 0; m < 4; m++) {
                int d = tx + 32 * m;
                g_pK[sp][(size_t)k * 128 + d] = aK[j][m];
                g_pV[sp][(size_t)k * 128 + d] = aV[j][m];
            }
        }
    }
}

// ---------------- kernel 3: reduce splits + |k_pot| ----------------
__global__ void k_reduceA(int K)
{
    int i = blockIdx.x * 256 + threadIdx.x;
    if (i >= K * 128) return;
    float kr = 0.f, ki = 0.f, vr = 0.f, vi = 0.f;
    #pragma unroll
    for (int s = 0; s < SPLIT_A; s++) {
        float2 a = up2(g_pK[s][i]);
        float2 b = up2(g_pV[s][i]);
        kr += a.x; ki += a.y; vr += b.x; vi += b.y;
    }
    g_kpr[i] = kr; g_kpi[i] = ki;
    g_vpr[i] = vr; g_vpi[i] = vi;
    g_akp[i] = sqrtf(kr*kr + ki*ki);
}

// ---------------- kernel 4: aw = |q| @ |k_pot|^T (packed over k) ----------------
__global__ void __launch_bounds__(256) k_phaseB(int K)
{
    __shared__ float s_a[16][132];  // [d][n]
    __shared__ float s_b[16][68];   // [d][k]

    const int t  = threadIdx.x;
    const int tx = t & 15;          // k cols tx*4..+3
    const int ty = t >> 4;          // n rows ty*8..+7
    const int kb = blockIdx.x * 64;
    const int nb = blockIdx.y * 128;

    u64 ac[8][2];
    #pragma unroll
    for (int i = 0; i < 8; i++) { ac[i][0] = 0ull; ac[i][1] = 0ull; }

    for (int d0 = 0; d0 < 128; d0 += 16) {
        __syncthreads();
        #pragma unroll
        for (int i = 0; i < 8; i++) {
            int r = ty + 16 * i;
            s_a[tx][r] = g_qabs[(size_t)(nb + r) * 128 + d0 + tx];
        }
        #pragma unroll
        for (int i = 0; i < 4; i++) {
            int r = ty + 16 * i;
            s_b[tx][r] = (kb + r < K) ? g_akp[(kb + r) * 128 + d0 + tx] : 0.f;
        }
        __syncthreads();
        #pragma unroll
        for (int dd = 0; dd < 16; dd++) {
            ulonglong2 b = *(const ulonglong2*)&s_b[dd][tx * 4];
            float4 a0 = *(const float4*)&s_a[dd][ty * 8];
            float4 a1 = *(const float4*)&s_a[dd][ty * 8 + 4];
            u64 A;
            A = dup2(a0.x); fma2(ac[0][0], A, b.x); fma2(ac[0][1], A, b.y);
            A = dup2(a0.y); fma2(ac[1][0], A, b.x); fma2(ac[1][1], A, b.y);
            A = dup2(a0.z); fma2(ac[2][0], A, b.x); fma2(ac[2][1], A, b.y);
            A = dup2(a0.w); fma2(ac[3][0], A, b.x); fma2(ac[3][1], A, b.y);
            A = dup2(a1.x); fma2(ac[4][0], A, b.x); fma2(ac[4][1], A, b.y);
            A = dup2(a1.y); fma2(ac[5][0], A, b.x); fma2(ac[5][1], A, b.y);
            A = dup2(a1.z); fma2(ac[6][0], A, b.x); fma2(ac[6][1], A, b.y);
            A = dup2(a1.w); fma2(ac[7][0], A, b.x); fma2(ac[7][1], A, b.y);
        }
    }
    #pragma unroll
    for (int i = 0; i < 8; i++) {
        int n = nb + ty * 8 + i;
        size_t base = (size_t)n * K + kb + tx * 4;
        float2 lo = up2(ac[i][0]), hi = up2(ac[i][1]);
        float vals[4] = {lo.x, lo.y, hi.x, hi.y};
        #pragma unroll
        for (int j = 0; j < 4; j++)
            if (kb + tx * 4 + j < K) g_aw[base + j] = vals[j];
    }
}

// ---------------- kernel 5: row softmax in place ----------------
__global__ void __launch_bounds__(256) k_softmax(int K)
{
    __shared__ float buf[K_MAX];
    __shared__ float red[8];
    const int n = blockIdx.x;
    const int t = threadIdx.x;
    float* row = g_aw + (size_t)n * K;

    float mx = -1e30f;
    for (int i = t; i < K; i += 256) { float v = row[i]; buf[i] = v; mx = fmaxf(mx, v); }
    #pragma unroll
    for (int o = 16; o; o >>= 1) mx = fmaxf(mx, __shfl_xor_sync(0xffffffffu, mx, o));
    if ((t & 31) == 0) red[t >> 5] = mx;
    __syncthreads();
    float gmax = red[0];
    #pragma unroll
    for (int j = 1; j < 8; j++) gmax = fmaxf(gmax, red[j]);
    __syncthreads();

    float s = 0.f;
    for (int i = t; i < K; i += 256) { float e = expf(buf[i] - gmax); buf[i] = e; s += e; }
    #pragma unroll
    for (int o = 16; o; o >>= 1) s += __shfl_xor_sync(0xffffffffu, s, o);
    if ((t & 31) == 0) red[t >> 5] = s;
    __syncthreads();
    float gsum = 0.f;
    #pragma unroll
    for (int j = 0; j < 8; j++) gsum += red[j];
    float inv = 1.f / gsum;
    for (int i = t; i < K; i += 256) row[i] = buf[i] * inv;
}

// ---------------- kernel 6: phase D (packed over d, split-K=2) ----------------
// tile 64n x 128d; thread: 4 n-rows x 4 d-pairs (pair p at d = 2*tx + 32*p)
__global__ void __launch_bounds__(256) k_phaseD(int K)
{
    __shared__ float2 s_w[64][32];      // [row][kk]  {sm*ci, sm*si}
    __shared__ float  s_vr[32][128];    // [kk][d]
    __shared__ float  s_vi[32][128];

    const int t  = threadIdx.x;
    const int tx = t & 15;              // d-pair lane
    const int ty = t >> 4;              // row group (rows ty*4+j)
    const int n0 = blockIdx.x * 64;
    const int z  = blockIdx.y;

    const int ksteps = (K + 31) / 32;
    const int half = (ksteps + 1) / 2;
    const int ks_lo = z ? half : 0;
    const int ks_hi = z ? ksteps : half;

    u64 acc[4][4];
    #pragma unroll
    for (int j = 0; j < 4; j++)
        #pragma unroll
        for (int p = 0; p < 4; p++) acc[j][p] = 0ull;

    for (int ks = ks_lo; ks < ks_hi; ks++) {
        const int k0 = ks * 32;
        __syncthreads();
        // fill w = sm * eik_i components
        #pragma unroll
        for (int j = 0; j < 8; j++) {
            int e = t + 256 * j;
            int row = e >> 5, kk = e & 31;
            float wr = 0.f, wi = 0.f;
            if (k0 + kk < K) {
                size_t gi = (size_t)(n0 + row) * K + k0 + kk;
                float sm = g_aw[gi];
                wr = sm * g_cosi[gi];
                wi = sm * g_sini[gi];
            }
            s_w[row][kk] = make_float2(wr, wi);
        }
        // fill v_pot tiles
        #pragma unroll
        for (int j = 0; j < 4; j++) {
            int lin = t + 256 * j;
            int kk = lin >> 5, c4 = lin & 31;
            float4 a = make_float4(0.f, 0.f, 0.f, 0.f);
            float4 b = make_float4(0.f, 0.f, 0.f, 0.f);
            if (k0 + kk < K) {
                a = *(const float4*)&g_vpr[(k0 + kk) * 128 + c4 * 4];
                b = *(const float4*)&g_vpi[(k0 + kk) * 128 + c4 * 4];
            }
            *(float4*)&s_vr[kk][c4 * 4] = a;
            *(float4*)&s_vi[kk][c4 * 4] = b;
        }
        __syncthreads();

        #pragma unroll
        for (int kk = 0; kk < 32; kk++) {
            u64 WR[4], WI[4];
            #pragma unroll
            for (int j = 0; j < 4; j++) {
                float2 w = s_w[ty * 4 + j][kk];
                WR[j] = dup2(w.x); WI[j] = dup2(w.y);
            }
            #pragma unroll
            for (int p = 0; p < 4; p++) {
                int d = 2 * tx + 32 * p;
                u64 vr = *(const u64*)&s_vr[kk][d];
                u64 vi = *(const u64*)&s_vi[kk][d];
                #pragma unroll
                for (int j = 0; j < 4; j++) {
                    fma2(acc[j][p], WR[j], vr);
                    fma2(acc[j][p], WI[j], vi);
                }
            }
        }
    }

    #pragma unroll
    for (int j = 0; j < 4; j++) {
        int row = n0 + ty * 4 + j;
        #pragma unroll
        for (int p = 0; p < 4; p++)
            g_pD[z][(size_t)row * 64 + tx + 16 * p] = acc[j][p];
    }
}

// ---------------- kernel 7: phase D reduce ----------------
__global__ void k_reduceD(float* __restrict__ out)
{
    int i = blockIdx.x * 256 + threadIdx.x;   // over N*64 u64 pairs
    float2 a = up2(g_pD[0][i]);
    float2 b = up2(g_pD[1][i]);
    ((float2*)out)[i] = make_float2(a.x + b.x, a.y + b.y);
}

// ---------------- launch ----------------
extern "C" void kernel_launch(void* const* d_in, const int* in_sizes, int n_in,
                              void* d_out, int out_size)
{
    const float* q    = (const float*)d_in[0];
    const float* kvec = (const float*)d_in[1];
    const float* vvec = (const float*)d_in[2];
    const float* pos  = (const float*)d_in[3];
    const float* cell = (const float*)d_in[4];
    const int*   kfwd = (const int*)d_in[6];
    const int*   kinv = (const int*)d_in[7];
    const int K = in_sizes[6] / 3;

    dim3 b(32, 8);
    k_build_fwd<<<N_ATOMS / 32, b>>>(pos, cell, kfwd, K);
    k_build_inv<<<N_ATOMS / 8, b>>>(pos, cell, kinv, K);
    k_absq<<<(N_ATOMS * D_DIM) / 256, 256>>>(q);

    dim3 gA((K + 31) / 32, SPLIT_A);
    k_phaseA<<<gA, 256>>>(kvec, vvec, K);
    k_reduceA<<<(K * D_DIM + 255) / 256, 256>>>(K);

    dim3 gB((K + 63) / 64, N_ATOMS / 128);
    k_phaseB<<<gB, 256>>>(K);
    k_softmax<<<N_ATOMS, 256>>>(K);

    dim3 gD(N_ATOMS / 64, 2);
    k_phaseD<<<gD, 256>>>(K);
    k_reduceD<<<(N_ATOMS * 64) / 256, 256>>>((float*)d_out);
}